// round 13
// baseline (speedup 1.0000x reference)
#include <cuda_runtime.h>
#include <cuda_bf16.h>
#include <cstdint>

typedef unsigned long long ULL;

// tcgen05 is an arch-SPECIFIC feature: legal in the sm_103a cubin pass,
// illegal in the generic compute_103 PTX pass the harness also emits.
#if !defined(__CUDA_ARCH__) || defined(__CUDA_ARCH_FEAT_SM103_ALL) || \
    defined(__CUDA_ARCH_FEAT_SM100_ALL) || defined(__CUDA_ARCH_SPECIFIC__) || \
    defined(__CUDA_ARCH_FAMILY_SPECIFIC__)
#define TC_OK 1
#else
#define TC_OK 0
#endif

// ---------------- f32x2 helpers (recurrence) ----------------
__device__ __forceinline__ void fma2(ULL& d, ULL a, ULL b) {
    asm("fma.rn.f32x2 %0, %1, %2, %0;" : "+l"(d) : "l"(a), "l"(b));
}
__device__ __forceinline__ ULL f2add(ULL a, ULL b) {
    ULL d;
    asm("add.rn.f32x2 %0, %1, %2;" : "=l"(d) : "l"(a), "l"(b));
    return d;
}
__device__ __forceinline__ float f2sum(ULL v) {
    float x, y;
    asm("mov.b64 {%0,%1}, %2;" : "=f"(x), "=f"(y) : "l"(v));
    return x + y;
}
__device__ __forceinline__ float sigf(float x) { return 1.f / (1.f + expf(-x)); }

// ---------------- tcgen05 helpers (guarded) ----------------
__device__ __forceinline__ uint32_t smem_u32(const void* p) {
    uint32_t a;
    asm("{ .reg .u64 t; cvta.to.shared.u64 t, %1; cvt.u32.u64 %0, t; }" : "=r"(a) : "l"(p));
    return a;
}
#define SW128(o) ((o) ^ (((o) >> 3) & 0x70))
static constexpr uint64_t DESC_BASE_SW128 =
    (uint64_t(2) << 61) | (uint64_t(1) << 46) | (uint64_t(64) << 32) | (uint64_t(1) << 16);
#define MKDESC(a) (DESC_BASE_SW128 | ((uint64_t)((a) >> 4) & 0x3FFF))

#if TC_OK
__device__ __forceinline__ uint32_t elect1() {
    uint32_t p;
    asm volatile("{\n\t.reg .pred p;\n\telect.sync _|p, 0xFFFFFFFF;\n\tselp.b32 %0, 1, 0, p;\n\t}" : "=r"(p));
    return p;
}
#define MBAR_INIT(m, c) asm volatile("mbarrier.init.shared.b64 [%0], %1;" :: "r"(m), "r"(c) : "memory")
#define MBAR_INVAL(m) asm volatile("mbarrier.inval.shared.b64 [%0];" :: "r"(m) : "memory")
#define MBAR_WAIT(m, ph) do { \
    uint32_t _m = (m), _p = (ph), _d; \
    asm volatile("{\n\t.reg .pred p;\n\tmbarrier.try_wait.parity.acquire.cta.shared::cta.b64 p, [%1], %2;\n\tselp.b32 %0,1,0,p;\n\t}" \
        : "=r"(_d) : "r"(_m), "r"(_p) : "memory"); \
    if (!_d) { asm volatile("{\n\t.reg .pred P1;\n\tWL%=:\n\tmbarrier.try_wait.parity.acquire.cta.shared::cta.b64 P1, [%0], %1, 0x989680;\n\t@P1 bra.uni WD%=;\n\tbra.uni WL%=;\n\tWD%=:\n\t}" :: "r"(_m), "r"(_p) : "memory"); } \
} while (0)
#define TC_ALLOC(sa, n)  asm volatile("tcgen05.alloc.cta_group::1.sync.aligned.shared::cta.b32 [%0], %1;" :: "r"(sa), "r"(n) : "memory")
#define TC_RELINQ()      asm volatile("tcgen05.relinquish_alloc_permit.cta_group::1.sync.aligned;")
#define TC_DEALLOC(t, n) asm volatile("tcgen05.dealloc.cta_group::1.sync.aligned.b32 %0, %1;" :: "r"(t), "r"(n))
#define TC_COMMIT(m)     asm volatile("tcgen05.commit.cta_group::1.mbarrier::arrive::one.shared::cluster.b64 [%0];" :: "r"(m) : "memory")
#define TC_WAIT_LD()     asm volatile("tcgen05.wait::ld.sync.aligned;" ::: "memory")
#define TC_FENCE_AFTER() asm volatile("tcgen05.fence::after_thread_sync;" ::: "memory")
#define TC_FENCE_BEFORE() asm volatile("tcgen05.fence::before_thread_sync;" ::: "memory")
#define FENCE_ASYNC()    asm volatile("fence.proxy.async.shared::cta;" ::: "memory")
#define TC_LD_X32(r, a) \
    asm volatile("tcgen05.ld.sync.aligned.32x32b.x32.b32 " \
        "{%0,%1,%2,%3,%4,%5,%6,%7,%8,%9,%10,%11,%12,%13,%14,%15," \
        "%16,%17,%18,%19,%20,%21,%22,%23,%24,%25,%26,%27,%28,%29,%30,%31}, [%32];" \
        : "=r"((r)[0]),"=r"((r)[1]),"=r"((r)[2]),"=r"((r)[3]),"=r"((r)[4]),"=r"((r)[5]),"=r"((r)[6]),"=r"((r)[7]), \
          "=r"((r)[8]),"=r"((r)[9]),"=r"((r)[10]),"=r"((r)[11]),"=r"((r)[12]),"=r"((r)[13]),"=r"((r)[14]),"=r"((r)[15]), \
          "=r"((r)[16]),"=r"((r)[17]),"=r"((r)[18]),"=r"((r)[19]),"=r"((r)[20]),"=r"((r)[21]),"=r"((r)[22]),"=r"((r)[23]), \
          "=r"((r)[24]),"=r"((r)[25]),"=r"((r)[26]),"=r"((r)[27]),"=r"((r)[28]),"=r"((r)[29]),"=r"((r)[30]),"=r"((r)[31]) \
        : "r"(a))
__device__ __forceinline__ void mma_f16_ss(uint32_t d, uint64_t ad, uint64_t bd, uint32_t idesc, uint32_t en) {
    asm volatile(
        "{\n\t.reg .pred p;\n\tsetp.ne.u32 p, %5, 0;\n\t"
        "tcgen05.mma.cta_group::1.kind::f16 [%0], %1, %2, %3, {%4, %4, %4, %4}, p;\n\t}"
        :: "r"(d), "l"(ad), "l"(bd), "r"(idesc), "r"(0u), "r"(en) : "memory");
}
#endif // TC_OK

// M=128, N=128, bf16 x bf16 -> f32
static constexpr uint32_t GEMM_IDESC = (1u << 4) | (1u << 7) | (1u << 10) | (16u << 17) | (8u << 24);

// ---------------- scratch ----------------
__device__ __nv_bfloat16 g_Ah[(size_t)32768 * 512];
__device__ __nv_bfloat16 g_Al[(size_t)32768 * 512];
__device__ __nv_bfloat16 g_Wh[2048 * 512];
__device__ __nv_bfloat16 g_Wl[2048 * 512];
__device__ float g_xg[(size_t)32768 * 2048];
__device__ float g_out1[32768 * 512];
__device__ float g_h[2 * 2 * 128 * 256];
__device__ float g_feats[(size_t)32768 * 22];
__device__ float g_nll[128];
__device__ unsigned g_bar[16];

// ---------------- release/acquire barrier primitives ----------------
__device__ __forceinline__ void bar_arrive_rel(unsigned* p) {
    asm volatile("red.release.gpu.global.add.u32 [%0], %1;" :: "l"(p), "r"(1u) : "memory");
}
__device__ __forceinline__ unsigned bar_ld_acq(unsigned* p) {
    unsigned v;
    asm volatile("ld.acquire.gpu.global.u32 %0, [%1];" : "=r"(v) : "l"(p) : "memory");
    return v;
}

// ---------------- embedding gather -> bf16 hi/lo (layer0 A, stride 256) ------
__global__ void embed_bf(const float* __restrict__ emb, const int* __restrict__ words) {
    int idx = blockIdx.x * 256 + threadIdx.x;
    int i = idx >> 8, e = idx & 255;
    float x = emb[(size_t)words[i] * 256 + e];
    __nv_bfloat16 h = __float2bfloat16_rn(x);
    g_Ah[idx] = h;
    g_Al[idx] = __float2bfloat16_rn(x - __bfloat162float(h));
}

// ---------------- fp32 -> bf16 hi/lo weight converter ----------------
__global__ void conv_w(const float* __restrict__ W) {
    size_t idx = (size_t)blockIdx.x * 256 + threadIdx.x;
    float x = W[idx];
    __nv_bfloat16 h = __float2bfloat16_rn(x);
    g_Wh[idx] = h;
    g_Wl[idx] = __float2bfloat16_rn(x - __bfloat162float(h));
}

// ---------------- tcgen05 input-projection GEMM (round-9, passing) ------------
#define GT_SMEM (1024 + 4 * 16384)
template <int K>
__global__ void __launch_bounds__(256, 2)
gemm_tc(const float* __restrict__ bi, const float* __restrict__ bh) {
#if TC_OK
    extern __shared__ char smx[];
    uint32_t sb = smem_u32(smx);
    const int SM_TM = 0, SM_MB = 8;
    const int SM_AH = 1024, SM_AL = SM_AH + 16384, SM_WH = SM_AL + 16384, SM_WL = SM_WH + 16384;

    int tid = threadIdx.x, wid = tid >> 5, lid = tid & 31;
    int nt = blockIdx.x, mt = blockIdx.y;

    if (wid == 0) {
        TC_ALLOC(sb + SM_TM, 128);
        TC_RELINQ();
    }
    if (tid == 0) MBAR_INIT(sb + SM_MB, 1);
    __syncthreads();
    uint32_t tmem;
    asm volatile("ld.shared.b32 %0, [%1];" : "=r"(tmem) : "r"(sb + SM_TM));

    const int NC = K / 64;
    for (int ci = 0; ci < NC; ++ci) {
#pragma unroll
        for (int i = 0; i < 4; ++i) {
            int idx = i * 256 + tid;
            int r = idx >> 3, c8 = idx & 7;
            uint32_t so = SW128((uint32_t)(r * 128 + c8 * 16));
            size_t ga = (size_t)(mt * 128 + r) * K + ci * 64 + c8 * 8;
            *(uint4*)(smx + SM_AH + so) = *(const uint4*)(g_Ah + ga);
            *(uint4*)(smx + SM_AL + so) = *(const uint4*)(g_Al + ga);
            size_t gw = (size_t)(nt * 128 + r) * K + ci * 64 + c8 * 8;
            *(uint4*)(smx + SM_WH + so) = *(const uint4*)(g_Wh + gw);
            *(uint4*)(smx + SM_WL + so) = *(const uint4*)(g_Wl + gw);
        }
        FENCE_ASYNC();
        __syncthreads();

        if (wid == 0 && elect1()) {
            uint64_t dAh = MKDESC(sb + SM_AH), dAl = MKDESC(sb + SM_AL);
            uint64_t dWh = MKDESC(sb + SM_WH), dWl = MKDESC(sb + SM_WL);
#pragma unroll
            for (int k = 0; k < 4; ++k) {
                uint64_t o = k * 2;
                mma_f16_ss(tmem, dAh + o, dWh + o, GEMM_IDESC, !(ci == 0 && k == 0));
                mma_f16_ss(tmem, dAh + o, dWl + o, GEMM_IDESC, 1u);
                mma_f16_ss(tmem, dAl + o, dWh + o, GEMM_IDESC, 1u);
            }
            TC_COMMIT(sb + SM_MB);
        }
        MBAR_WAIT(sb + SM_MB, (uint32_t)(ci & 1));
        __syncthreads();
    }

    TC_FENCE_AFTER();
    if (wid < 4) {
        int m = mt * 128 + wid * 32 + lid;
#pragma unroll
        for (int nb = 0; nb < 4; ++nb) {
            uint32_t dr[32];
            TC_LD_X32(dr, tmem + nb * 32);
            TC_WAIT_LD();
            int n0 = nt * 128 + nb * 32;
#pragma unroll
            for (int c8 = 0; c8 < 8; ++c8) {
                float4 o;
                int n = n0 + c8 * 4;
                o.x = __uint_as_float(dr[c8 * 4 + 0]) + bi[n + 0] + bh[n + 0];
                o.y = __uint_as_float(dr[c8 * 4 + 1]) + bi[n + 1] + bh[n + 1];
                o.z = __uint_as_float(dr[c8 * 4 + 2]) + bi[n + 2] + bh[n + 2];
                o.w = __uint_as_float(dr[c8 * 4 + 3]) + bi[n + 3] + bh[n + 3];
                *(float4*)&g_xg[(size_t)m * 2048 + n] = o;
            }
        }
    }
    TC_FENCE_BEFORE();
    __syncthreads();
    if (tid == 0) MBAR_INVAL(sb + SM_MB);
    if (wid == 0) TC_DEALLOC(tmem, 128);
#else
    // Correct SIMT fallback for the generic compute_103 PTX pass (never runs).
    int tid = threadIdx.x;
    int nt = blockIdx.x, mt = blockIdx.y;
    for (int q = tid; q < 128 * 128; q += 256) {
        int mi = q >> 7, ni = q & 127;
        int m = mt * 128 + mi, n = nt * 128 + ni;
        float s = 0.f;
        for (int k = 0; k < K; ++k) {
            float a = __bfloat162float(g_Ah[(size_t)m * K + k]) + __bfloat162float(g_Al[(size_t)m * K + k]);
            float w = __bfloat162float(g_Wh[(size_t)n * K + k]) + __bfloat162float(g_Wl[(size_t)n * K + k]);
            s += a * w;
        }
        g_xg[(size_t)m * 2048 + n] = s + bi[n] + bh[n];
    }
#endif
}

// ---------------- zero h pings + group barriers ----------------
__global__ void init_hc() {
    int i = blockIdx.x * 256 + threadIdx.x;   // 128 blocks: 32768 float4
    *(float4*)&g_h[i * 4] = make_float4(0.f, 0.f, 0.f, 0.f);
    if (i < 16) g_bar[i] = 0u;
}

// ---------------- persistent BiLSTM layer v8: dual-direction interleave -------
// 128 blocks = bch(8 groups of 16 batches) x uch(16 chunks of 16 units); each
// block handles BOTH directions of its slice, alternating phases per timestep.
// The group-barrier wait for dir d sits a full opposite-dir phase after its
// arrive -> barrier latency + skew fully hidden.
// 512 threads: wg = tid>>6 splits K 8 ways (32 k); wtid = tid&63: u = wtid&15,
// bg = wtid>>4 (4 groups x 4 batches). Epilogue: thread owns one (dir,b,u)
// cell (tid>>8 = dir). Barrier groups: 16 = dir*8+bch, 16 arrivals each.
#define PERS_SMEM ((128 * 260 + 16 * 260) * 4 + 8 * 64 * 17 * 8)
__global__ void __launch_bounds__(512) lstm_persist(const float* __restrict__ whh, int layer) {
    extern __shared__ float sm[];
    float* ws = sm;                        // [128][260] row = d*64 + g*16 + u
    float* hs = sm + 128 * 260;            // [16][260]
    ULL* part = (ULL*)(sm + 144 * 260);    // [8 wg][64 wtid][17]

    int bx = blockIdx.x;
    int bch = bx & 7, uch = bx >> 3;
    int tid = threadIdx.x;
    int wg = tid >> 6, wtid = tid & 63;
    int u = wtid & 15, bg = wtid >> 4;
    const int kbase = wg * 32;

    // epilogue cell: one (dir, batch, unit) per thread
    int edir = tid >> 8;
    int u_l = tid & 15, b_l = (tid >> 4) & 15;
    int uu_e = uch * 16 + u_l, b_e = bch * 16 + b_l;
    int src = (b_l >> 2) * 16 + u_l, jj = b_l & 3;

    // stage W_hh slices for BOTH dirs: 128 rows x 256 k = 16384 float2
#pragma unroll 4
    for (int r = 0; r < 32; ++r) {
        int q = r * 512 + tid;
        int wrow = q >> 7, cc = q & 127;
        int dw = wrow >> 6, rr = wrow & 63;
        int g = rr >> 4, uw = rr & 15;
        *(float2*)&ws[wrow * 260 + cc * 2] =
            *(const float2*)&whh[((size_t)dw * 1024 + g * 256 + uch * 16 + uw) * 256 + cc * 2];
    }

    float creg = 0.f;
    float xg[4];
    {
        int td0 = edir ? 255 : 0;
        size_t xb = ((size_t)b_e * 256 + td0) * 2048 + edir * 1024 + uu_e;
        xg[0] = __ldcg(&g_xg[xb]);
        xg[1] = __ldcg(&g_xg[xb + 256]);
        xg[2] = __ldcg(&g_xg[xb + 512]);
        xg[3] = __ldcg(&g_xg[xb + 768]);
    }

    for (int t = 0; t < 256; ++t) {
#pragma unroll
        for (int d = 0; d < 2; ++d) {
            int td = d ? 255 - t : t;
            const float* hin = g_h + (t & 1) * (2 * 128 * 256) + (d * 128 + bch * 16) * 256;
            float* hout = g_h + ((t & 1) ^ 1) * (2 * 128 * 256);
            unsigned* bar = &g_bar[d * 8 + bch];

            // wait for all h(t-1,dir d) stores (arrive was a full phase ago)
            if (tid == 0 && t > 0) {
                unsigned tgt = 16u * (unsigned)t;
                while (bar_ld_acq(bar) < tgt) { }
            }
            __syncthreads();

            // stage h_{t-1}(dir d): 16 batches x 256 k = 2048 float2
#pragma unroll
            for (int r = 0; r < 4; ++r) {
                int q = r * 512 + tid;
                int row = q >> 7, cc = q & 127;
                *(float2*)&hs[row * 260 + cc * 2] = __ldcg((const float2*)&hin[row * 256 + cc * 2]);
            }
            __syncthreads();

            ULL acc[4][4] = {};
#pragma unroll
            for (int kq = 0; kq < 8; ++kq) {
                ulonglong2 hv[4], wv[4];
#pragma unroll
                for (int j = 0; j < 4; ++j)
                    hv[j] = *(const ulonglong2*)&hs[(bg * 4 + j) * 260 + kbase + kq * 4];
#pragma unroll
                for (int g = 0; g < 4; ++g)
                    wv[g] = *(const ulonglong2*)&ws[(d * 64 + g * 16 + u) * 260 + kbase + kq * 4];
#pragma unroll
                for (int g = 0; g < 4; ++g)
#pragma unroll
                    for (int j = 0; j < 4; ++j) {
                        fma2(acc[g][j], hv[j].x, wv[g].x);
                        fma2(acc[g][j], hv[j].y, wv[g].y);
                    }
            }
            {
                ULL* pp = &part[(wg * 64 + wtid) * 17];
#pragma unroll
                for (int g = 0; g < 4; ++g)
#pragma unroll
                    for (int j = 0; j < 4; ++j) pp[g * 4 + j] = acc[g][j];
            }
            __syncthreads();

            // epilogue on the dir-d half of the block
            float hn = 0.f;
            if (edir == d) {
                float gv[4];
#pragma unroll
                for (int g = 0; g < 4; ++g) {
                    ULL s = part[src * 17 + g * 4 + jj];
#pragma unroll
                    for (int w = 1; w < 8; ++w)
                        s = f2add(s, part[(w * 64 + src) * 17 + g * 4 + jj]);
                    gv[g] = f2sum(s) + xg[g];
                }
                float cn = sigf(gv[1]) * creg + sigf(gv[0]) * tanhf(gv[2]);
                hn = sigf(gv[3]) * tanhf(cn);
                creg = cn;
                hout[(d * 128 + b_e) * 256 + uu_e] = hn;
            }
            __syncthreads();

            if (tid == 0) bar_arrive_rel(bar);
            // shadow work hidden behind the opposite-dir phase
            if (edir == d) {
                size_t oi = ((size_t)b_e * 256 + td) * 512 + d * 256 + uu_e;
                if (layer == 0) {
                    __nv_bfloat16 hh = __float2bfloat16_rn(hn);
                    g_Ah[oi] = hh;
                    g_Al[oi] = __float2bfloat16_rn(hn - __bfloat162float(hh));
                } else {
                    g_out1[oi] = hn;
                }
                if (t + 1 < 256) {
                    int td2 = d ? 255 - (t + 1) : t + 1;
                    size_t xb = ((size_t)b_e * 256 + td2) * 2048 + d * 1024 + uu_e;
                    xg[0] = __ldcg(&g_xg[xb]);
                    xg[1] = __ldcg(&g_xg[xb + 256]);
                    xg[2] = __ldcg(&g_xg[xb + 512]);
                    xg[3] = __ldcg(&g_xg[xb + 768]);
                }
            }
        }
    }
}

// ---------------- LayerNorm + output projection (16 tokens/block) -------------
#define LN_SMEM (22 * 512 * 4 + 2 * 512 * 4 + 2 * 16 * 4 + 32 * 4)
__global__ void __launch_bounds__(256) lnfeats16(const float* __restrict__ lng,
                                                 const float* __restrict__ lnb,
                                                 const float* __restrict__ wo,
                                                 const float* __restrict__ bo) {
    extern __shared__ float lsm[];
    float* wos = lsm;                 // [22][512]
    float* row = lsm + 22 * 512;      // [2][512]
    float* red = row + 2 * 512;       // [2][16]
    float* bos = red + 2 * 16;        // [32]

    int tid = threadIdx.x;
    for (int q = tid; q < 22 * 512; q += 256) wos[q] = wo[q];
    if (tid < 22) bos[tid] = bo[tid];
    __syncthreads();

    int half = tid >> 7, t128 = tid & 127;
    int wid = t128 >> 5, lane = t128 & 31;

    for (int it = 0; it < 8; ++it) {
        int i = blockIdx.x * 16 + it * 2 + half;
        float4 v = *(const float4*)&g_out1[(size_t)i * 512 + t128 * 4];
        float s = v.x + v.y + v.z + v.w;
        float q = v.x * v.x + v.y * v.y + v.z * v.z + v.w * v.w;
#pragma unroll
        for (int o = 16; o; o >>= 1) {
            s += __shfl_xor_sync(0xffffffffu, s, o);
            q += __shfl_xor_sync(0xffffffffu, q, o);
        }
        if (!lane) { red[half * 16 + wid] = s; red[half * 16 + 4 + wid] = q; }
        __syncthreads();
        if (t128 == 0) {
            float S = red[half * 16 + 0] + red[half * 16 + 1] + red[half * 16 + 2] + red[half * 16 + 3];
            float Q = red[half * 16 + 4] + red[half * 16 + 5] + red[half * 16 + 6] + red[half * 16 + 7];
            float mu = S / 512.f;
            float var = Q / 512.f - mu * mu;
            red[half * 16 + 8] = mu;
            red[half * 16 + 9] = rsqrtf(var + 1e-5f);
        }
        __syncthreads();
        float mu = red[half * 16 + 8], rs = red[half * 16 + 9];
        int k = t128 * 4;
        float* rw = &row[half * 512];
        rw[k + 0] = (v.x - mu) * rs * lng[k + 0] + lnb[k + 0];
        rw[k + 1] = (v.y - mu) * rs * lng[k + 1] + lnb[k + 1];
        rw[k + 2] = (v.z - mu) * rs * lng[k + 2] + lnb[k + 2];
        rw[k + 3] = (v.w - mu) * rs * lng[k + 3] + lnb[k + 3];
        __syncthreads();
        for (int o = wid; o < 22; o += 4) {
            float a = 0.f;
            const float* wr = &wos[o * 512];
            for (int k2 = lane; k2 < 512; k2 += 32) a += rw[k2] * wr[k2];
#pragma unroll
            for (int off = 16; off; off >>= 1) a += __shfl_xor_sync(0xffffffffu, a, off);
            if (!lane) g_feats[(size_t)i * 22 + o] = a + bos[o];
        }
        __syncthreads();
    }
}

// ---------------- CRF forward + scores (one warp per batch) -------------------
__global__ void crf_k(const float* __restrict__ trans, const int* __restrict__ mask,
                      const int* __restrict__ tags) {
    __shared__ float tr[484];
    __shared__ float alpha[22];
    int b = blockIdx.x, j = threadIdx.x;
    for (int q = j; q < 484; q += 32) tr[q] = trans[q];
    const float* Fb = g_feats + (size_t)b * 256 * 22;
    __syncwarp();
    if (j < 22) alpha[j] = tr[20 * 22 + j] + Fb[j];
    __syncwarp();
    for (int t = 1; t < 256; ++t) {
        float aj = 0.f;
        if (j < 22) {
            float m = -1e30f;
#pragma unroll
            for (int i2 = 0; i2 < 22; ++i2) m = fmaxf(m, alpha[i2] + tr[i2 * 22 + j]);
            float sm = 0.f;
#pragma unroll
            for (int i2 = 0; i2 < 22; ++i2) sm += expf(alpha[i2] + tr[i2 * 22 + j] - m);
            aj = m + logf(sm) + Fb[t * 22 + j];
        }
        int mt = mask[b * 256 + t];
        __syncwarp();
        if (j < 22 && mt) alpha[j] = aj;
        __syncwarp();
    }
    float v = (j < 22) ? alpha[j] + tr[j * 22 + 21] : -1e30f;
    float m = v;
#pragma unroll
    for (int off = 16; off; off >>= 1) m = fmaxf(m, __shfl_xor_sync(0xffffffffu, m, off));
    float e = (j < 22) ? expf(v - m) : 0.f;
#pragma unroll
    for (int off = 16; off; off >>= 1) e += __shfl_xor_sync(0xffffffffu, e, off);
    float logZ = m + logf(e);

    const int* tg = tags + (size_t)b * 256;
    const int* mk = mask + b * 256;
    float emit = 0.f, trs = 0.f;
    int cnt = 0;
    for (int t = j; t < 256; t += 32) {
        if (mk[t]) {
            emit += Fb[t * 22 + tg[t]];
            cnt++;
            if (t >= 1) trs += tr[tg[t - 1] * 22 + tg[t]];
        }
    }
#pragma unroll
    for (int off = 16; off; off >>= 1) {
        emit += __shfl_xor_sync(0xffffffffu, emit, off);
        trs += __shfl_xor_sync(0xffffffffu, trs, off);
        cnt += __shfl_xor_sync(0xffffffffu, cnt, off);
    }
    if (!j) {
        trs += tr[20 * 22 + tg[0]];
        trs += tr[tg[cnt - 1] * 22 + 21];
        g_nll[b] = logZ - emit - trs;
    }
}

__global__ void reduce_nll(float* out) {
    int tid = threadIdx.x;
    float v = g_nll[tid];
#pragma unroll
    for (int off = 16; off; off >>= 1) v += __shfl_xor_sync(0xffffffffu, v, off);
    __shared__ float r[4];
    if (!(tid & 31)) r[tid >> 5] = v;
    __syncthreads();
    if (!tid) out[0] = (r[0] + r[1] + r[2] + r[3]) / 128.f;
}

// ---------------- launcher ----------------
extern "C" void kernel_launch(void* const* d_in, const int* in_sizes, int n_in,
                              void* d_out, int out_size) {
    const float* emb    = (const float*)d_in[0];
    const float* w_ih0  = (const float*)d_in[1];
    const float* w_hh0  = (const float*)d_in[2];
    const float* b_ih0  = (const float*)d_in[3];
    const float* b_hh0  = (const float*)d_in[4];
    const float* w_ih1  = (const float*)d_in[5];
    const float* w_hh1  = (const float*)d_in[6];
    const float* b_ih1  = (const float*)d_in[7];
    const float* b_hh1  = (const float*)d_in[8];
    const float* ln_g   = (const float*)d_in[9];
    const float* ln_b   = (const float*)d_in[10];
    const float* w_out  = (const float*)d_in[11];
    const float* b_out  = (const float*)d_in[12];
    const float* trans  = (const float*)d_in[13];
    const int* words    = (const int*)d_in[14];
    const int* mask     = (const int*)d_in[15];
    const int* tags     = (const int*)d_in[16];
    float* out = (float*)d_out;

    cudaFuncSetAttribute(lstm_persist, cudaFuncAttributeMaxDynamicSharedMemorySize, PERS_SMEM);
    cudaFuncSetAttribute(gemm_tc<256>, cudaFuncAttributeMaxDynamicSharedMemorySize, GT_SMEM);
    cudaFuncSetAttribute(gemm_tc<512>, cudaFuncAttributeMaxDynamicSharedMemorySize, GT_SMEM);
    cudaFuncSetAttribute(lnfeats16, cudaFuncAttributeMaxDynamicSharedMemorySize, LN_SMEM);

    // layer 0
    embed_bf<<<32768, 256>>>(emb, words);
    conv_w<<<2048, 256>>>(w_ih0);
    gemm_tc<256><<<dim3(16, 256), 256, GT_SMEM>>>(b_ih0, b_hh0);
    init_hc<<<128, 256>>>();
    lstm_persist<<<128, 512, PERS_SMEM>>>(w_hh0, 0);   // writes bf16 hi/lo out
    // layer 1
    conv_w<<<4096, 256>>>(w_ih1);
    gemm_tc<512><<<dim3(16, 256), 256, GT_SMEM>>>(b_ih1, b_hh1);
    init_hc<<<128, 256>>>();
    lstm_persist<<<128, 512, PERS_SMEM>>>(w_hh1, 1);
    // head
    lnfeats16<<<2048, 256, LN_SMEM>>>(ln_g, ln_b, w_out, b_out);
    crf_k<<<128, 32>>>(trans, mask, tags);
    reduce_nll<<<1, 128>>>(out);
}

// round 14
// speedup vs baseline: 1.2645x; 1.2645x over previous
#include <cuda_runtime.h>
#include <cuda_bf16.h>
#include <cstdint>

typedef unsigned long long ULL;

// tcgen05 is an arch-SPECIFIC feature: legal in the sm_103a cubin pass,
// illegal in the generic compute_103 PTX pass the harness also emits.
#if !defined(__CUDA_ARCH__) || defined(__CUDA_ARCH_FEAT_SM103_ALL) || \
    defined(__CUDA_ARCH_FEAT_SM100_ALL) || defined(__CUDA_ARCH_SPECIFIC__) || \
    defined(__CUDA_ARCH_FAMILY_SPECIFIC__)
#define TC_OK 1
#else
#define TC_OK 0
#endif

// ---------------- f32x2 helpers (recurrence) ----------------
__device__ __forceinline__ void fma2(ULL& d, ULL a, ULL b) {
    asm("fma.rn.f32x2 %0, %1, %2, %0;" : "+l"(d) : "l"(a), "l"(b));
}
__device__ __forceinline__ ULL f2add(ULL a, ULL b) {
    ULL d;
    asm("add.rn.f32x2 %0, %1, %2;" : "=l"(d) : "l"(a), "l"(b));
    return d;
}
__device__ __forceinline__ float f2sum(ULL v) {
    float x, y;
    asm("mov.b64 {%0,%1}, %2;" : "=f"(x), "=f"(y) : "l"(v));
    return x + y;
}
__device__ __forceinline__ float sigf(float x) { return 1.f / (1.f + expf(-x)); }

// bf16 hi/lo pack helpers (xg compression)
__device__ __forceinline__ unsigned xg_pack(float x) {
    __nv_bfloat162 p;
    p.x = __float2bfloat16_rn(x);
    p.y = __float2bfloat16_rn(x - __bfloat162float(p.x));
    return *reinterpret_cast<unsigned*>(&p);
}
__device__ __forceinline__ float xg_unpack(unsigned v) {
    __nv_bfloat162 p = *reinterpret_cast<__nv_bfloat162*>(&v);
    return __bfloat162float(p.x) + __bfloat162float(p.y);
}

// ---------------- tcgen05 helpers (guarded) ----------------
__device__ __forceinline__ uint32_t smem_u32(const void* p) {
    uint32_t a;
    asm("{ .reg .u64 t; cvta.to.shared.u64 t, %1; cvt.u32.u64 %0, t; }" : "=r"(a) : "l"(p));
    return a;
}
#define SW128(o) ((o) ^ (((o) >> 3) & 0x70))
static constexpr uint64_t DESC_BASE_SW128 =
    (uint64_t(2) << 61) | (uint64_t(1) << 46) | (uint64_t(64) << 32) | (uint64_t(1) << 16);
#define MKDESC(a) (DESC_BASE_SW128 | ((uint64_t)((a) >> 4) & 0x3FFF))

#if TC_OK
__device__ __forceinline__ uint32_t elect1() {
    uint32_t p;
    asm volatile("{\n\t.reg .pred p;\n\telect.sync _|p, 0xFFFFFFFF;\n\tselp.b32 %0, 1, 0, p;\n\t}" : "=r"(p));
    return p;
}
#define MBAR_INIT(m, c) asm volatile("mbarrier.init.shared.b64 [%0], %1;" :: "r"(m), "r"(c) : "memory")
#define MBAR_INVAL(m) asm volatile("mbarrier.inval.shared.b64 [%0];" :: "r"(m) : "memory")
#define MBAR_WAIT(m, ph) do { \
    uint32_t _m = (m), _p = (ph), _d; \
    asm volatile("{\n\t.reg .pred p;\n\tmbarrier.try_wait.parity.acquire.cta.shared::cta.b64 p, [%1], %2;\n\tselp.b32 %0,1,0,p;\n\t}" \
        : "=r"(_d) : "r"(_m), "r"(_p) : "memory"); \
    if (!_d) { asm volatile("{\n\t.reg .pred P1;\n\tWL%=:\n\tmbarrier.try_wait.parity.acquire.cta.shared::cta.b64 P1, [%0], %1, 0x989680;\n\t@P1 bra.uni WD%=;\n\tbra.uni WL%=;\n\tWD%=:\n\t}" :: "r"(_m), "r"(_p) : "memory"); } \
} while (0)
#define TC_ALLOC(sa, n)  asm volatile("tcgen05.alloc.cta_group::1.sync.aligned.shared::cta.b32 [%0], %1;" :: "r"(sa), "r"(n) : "memory")
#define TC_RELINQ()      asm volatile("tcgen05.relinquish_alloc_permit.cta_group::1.sync.aligned;")
#define TC_DEALLOC(t, n) asm volatile("tcgen05.dealloc.cta_group::1.sync.aligned.b32 %0, %1;" :: "r"(t), "r"(n))
#define TC_COMMIT(m)     asm volatile("tcgen05.commit.cta_group::1.mbarrier::arrive::one.shared::cluster.b64 [%0];" :: "r"(m) : "memory")
#define TC_WAIT_LD()     asm volatile("tcgen05.wait::ld.sync.aligned;" ::: "memory")
#define TC_FENCE_AFTER() asm volatile("tcgen05.fence::after_thread_sync;" ::: "memory")
#define TC_FENCE_BEFORE() asm volatile("tcgen05.fence::before_thread_sync;" ::: "memory")
#define FENCE_ASYNC()    asm volatile("fence.proxy.async.shared::cta;" ::: "memory")
#define TC_LD_X32(r, a) \
    asm volatile("tcgen05.ld.sync.aligned.32x32b.x32.b32 " \
        "{%0,%1,%2,%3,%4,%5,%6,%7,%8,%9,%10,%11,%12,%13,%14,%15," \
        "%16,%17,%18,%19,%20,%21,%22,%23,%24,%25,%26,%27,%28,%29,%30,%31}, [%32];" \
        : "=r"((r)[0]),"=r"((r)[1]),"=r"((r)[2]),"=r"((r)[3]),"=r"((r)[4]),"=r"((r)[5]),"=r"((r)[6]),"=r"((r)[7]), \
          "=r"((r)[8]),"=r"((r)[9]),"=r"((r)[10]),"=r"((r)[11]),"=r"((r)[12]),"=r"((r)[13]),"=r"((r)[14]),"=r"((r)[15]), \
          "=r"((r)[16]),"=r"((r)[17]),"=r"((r)[18]),"=r"((r)[19]),"=r"((r)[20]),"=r"((r)[21]),"=r"((r)[22]),"=r"((r)[23]), \
          "=r"((r)[24]),"=r"((r)[25]),"=r"((r)[26]),"=r"((r)[27]),"=r"((r)[28]),"=r"((r)[29]),"=r"((r)[30]),"=r"((r)[31]) \
        : "r"(a))
__device__ __forceinline__ void mma_f16_ss(uint32_t d, uint64_t ad, uint64_t bd, uint32_t idesc, uint32_t en) {
    asm volatile(
        "{\n\t.reg .pred p;\n\tsetp.ne.u32 p, %5, 0;\n\t"
        "tcgen05.mma.cta_group::1.kind::f16 [%0], %1, %2, %3, {%4, %4, %4, %4}, p;\n\t}"
        :: "r"(d), "l"(ad), "l"(bd), "r"(idesc), "r"(0u), "r"(en) : "memory");
}
#endif // TC_OK

// M=128, N=256, bf16 x bf16 -> f32
static constexpr uint32_t GEMM_IDESC = (1u << 4) | (1u << 7) | (1u << 10) | (32u << 17) | (8u << 24);

// ---------------- scratch ----------------
__device__ __nv_bfloat16 g_Ah[(size_t)32768 * 512];
__device__ __nv_bfloat16 g_Al[(size_t)32768 * 512];
__device__ __nv_bfloat16 g_Wh[2048 * 512];
__device__ __nv_bfloat16 g_Wl[2048 * 512];
__device__ unsigned g_xg[(size_t)32768 * 2048];   // packed bf16 hi/lo per gate bias
__device__ float g_out1[32768 * 512];
__device__ float g_h[2 * 2 * 128 * 256];
__device__ float g_feats[(size_t)32768 * 22];
__device__ float g_nll[128];
__device__ unsigned g_bar[16];

// ---------------- release/acquire barrier primitives ----------------
__device__ __forceinline__ void bar_arrive_rel(unsigned* p) {
    asm volatile("red.release.gpu.global.add.u32 [%0], %1;" :: "l"(p), "r"(1u) : "memory");
}
__device__ __forceinline__ unsigned bar_ld_acq(unsigned* p) {
    unsigned v;
    asm volatile("ld.acquire.gpu.global.u32 %0, [%1];" : "=r"(v) : "l"(p) : "memory");
    return v;
}

// ---------------- embedding gather -> bf16 hi/lo (layer0 A, stride 256) ------
__global__ void embed_bf(const float* __restrict__ emb, const int* __restrict__ words) {
    int idx = blockIdx.x * 256 + threadIdx.x;
    int i = idx >> 8, e = idx & 255;
    float x = emb[(size_t)words[i] * 256 + e];
    __nv_bfloat16 h = __float2bfloat16_rn(x);
    g_Ah[idx] = h;
    g_Al[idx] = __float2bfloat16_rn(x - __bfloat162float(h));
}

// ---------------- fp32 -> bf16 hi/lo weight converter ----------------
__global__ void conv_w(const float* __restrict__ W) {
    size_t idx = (size_t)blockIdx.x * 256 + threadIdx.x;
    float x = W[idx];
    __nv_bfloat16 h = __float2bfloat16_rn(x);
    g_Wh[idx] = h;
    g_Wl[idx] = __float2bfloat16_rn(x - __bfloat162float(h));
}

// ---------------- tcgen05 input-projection GEMM, m128 x n256 tiles ------------
// C[32768][2048] = A[32768][K] * W[2048][K]^T + (bi + bh), bf16-split 3-product.
// n256 halves A DRAM re-reads vs n128. Output packed bf16 hi/lo (u32).
#define GT_SMEM (1024 + 2 * 16384 + 2 * 32768)
template <int K>
__global__ void __launch_bounds__(256, 2)
gemm_tc(const float* __restrict__ bi, const float* __restrict__ bh) {
#if TC_OK
    extern __shared__ char smx[];
    uint32_t sb = smem_u32(smx);
    const int SM_TM = 0, SM_MB = 8;
    const int SM_AH = 1024, SM_AL = SM_AH + 16384, SM_WH = SM_AL + 16384, SM_WL = SM_WH + 32768;

    int tid = threadIdx.x, wid = tid >> 5, lid = tid & 31;
    int nt = blockIdx.x, mt = blockIdx.y;

    if (wid == 0) {
        TC_ALLOC(sb + SM_TM, 256);
        TC_RELINQ();
    }
    if (tid == 0) MBAR_INIT(sb + SM_MB, 1);
    __syncthreads();
    uint32_t tmem;
    asm volatile("ld.shared.b32 %0, [%1];" : "=r"(tmem) : "r"(sb + SM_TM));

    const int NC = K / 64;
    for (int ci = 0; ci < NC; ++ci) {
        // stage A hi/lo: 128 rows x 64 bf16 each (1024 uint4 per array)
#pragma unroll
        for (int i = 0; i < 4; ++i) {
            int idx = i * 256 + tid;
            int r = idx >> 3, c8 = idx & 7;
            uint32_t so = SW128((uint32_t)(r * 128 + c8 * 16));
            size_t ga = (size_t)(mt * 128 + r) * K + ci * 64 + c8 * 8;
            *(uint4*)(smx + SM_AH + so) = *(const uint4*)(g_Ah + ga);
            *(uint4*)(smx + SM_AL + so) = *(const uint4*)(g_Al + ga);
        }
        // stage W hi/lo: 256 rows x 64 bf16 each (2048 uint4 per array)
#pragma unroll
        for (int i = 0; i < 8; ++i) {
            int idx = i * 256 + tid;
            int r = idx >> 3, c8 = idx & 7;
            uint32_t so = SW128((uint32_t)(r * 128 + c8 * 16));
            size_t gw = (size_t)(nt * 256 + r) * K + ci * 64 + c8 * 8;
            *(uint4*)(smx + SM_WH + so) = *(const uint4*)(g_Wh + gw);
            *(uint4*)(smx + SM_WL + so) = *(const uint4*)(g_Wl + gw);
        }
        FENCE_ASYNC();
        __syncthreads();

        if (wid == 0 && elect1()) {
            uint64_t dAh = MKDESC(sb + SM_AH), dAl = MKDESC(sb + SM_AL);
            uint64_t dWh = MKDESC(sb + SM_WH), dWl = MKDESC(sb + SM_WL);
#pragma unroll
            for (int k = 0; k < 4; ++k) {
                uint64_t o = k * 2;
                mma_f16_ss(tmem, dAh + o, dWh + o, GEMM_IDESC, !(ci == 0 && k == 0));
                mma_f16_ss(tmem, dAh + o, dWl + o, GEMM_IDESC, 1u);
                mma_f16_ss(tmem, dAl + o, dWh + o, GEMM_IDESC, 1u);
            }
            TC_COMMIT(sb + SM_MB);
        }
        MBAR_WAIT(sb + SM_MB, (uint32_t)(ci & 1));
        __syncthreads();
    }

    TC_FENCE_AFTER();
    if (wid < 4) {
        int m = mt * 128 + wid * 32 + lid;
#pragma unroll
        for (int nb = 0; nb < 8; ++nb) {
            uint32_t dr[32];
            TC_LD_X32(dr, tmem + nb * 32);
            TC_WAIT_LD();
            int n0 = nt * 256 + nb * 32;
#pragma unroll
            for (int c4 = 0; c4 < 8; ++c4) {
                uint4 o;
                int n = n0 + c4 * 4;
                o.x = xg_pack(__uint_as_float(dr[c4 * 4 + 0]) + bi[n + 0] + bh[n + 0]);
                o.y = xg_pack(__uint_as_float(dr[c4 * 4 + 1]) + bi[n + 1] + bh[n + 1]);
                o.z = xg_pack(__uint_as_float(dr[c4 * 4 + 2]) + bi[n + 2] + bh[n + 2]);
                o.w = xg_pack(__uint_as_float(dr[c4 * 4 + 3]) + bi[n + 3] + bh[n + 3]);
                *(uint4*)&g_xg[(size_t)m * 2048 + n] = o;
            }
        }
    }
    TC_FENCE_BEFORE();
    __syncthreads();
    if (tid == 0) MBAR_INVAL(sb + SM_MB);
    if (wid == 0) TC_DEALLOC(tmem, 256);
#else
    // Correct SIMT fallback for the generic compute_103 PTX pass (never runs).
    int tid = threadIdx.x;
    int nt = blockIdx.x, mt = blockIdx.y;
    for (int q = tid; q < 128 * 256; q += 256) {
        int mi = q >> 8, ni = q & 255;
        int m = mt * 128 + mi, n = nt * 256 + ni;
        float s = 0.f;
        for (int k = 0; k < K; ++k) {
            float a = __bfloat162float(g_Ah[(size_t)m * K + k]) + __bfloat162float(g_Al[(size_t)m * K + k]);
            float w = __bfloat162float(g_Wh[(size_t)n * K + k]) + __bfloat162float(g_Wl[(size_t)n * K + k]);
            s += a * w;
        }
        g_xg[(size_t)m * 2048 + n] = xg_pack(s + bi[n] + bh[n]);
    }
#endif
}

// ---------------- zero h pings + group barriers ----------------
__global__ void init_hc() {
    int i = blockIdx.x * 256 + threadIdx.x;   // 128 blocks: 32768 float4
    *(float4*)&g_h[i * 4] = make_float4(0.f, 0.f, 0.f, 0.f);
    if (i < 16) g_bar[i] = 0u;
}

// ---------------- persistent BiLSTM layer (round-12 proven version) -----------
// 128 blocks: bx bit0 = dir, bits1-3 = bch (8 groups of 16 batches),
// bits4-6 = uch (8 chunks of 32 units). Barrier group = (dir,bch) -> 8 blocks.
// 512 threads: wg = tid>>7 splits K 4 ways; wtid = tid&127: u = wtid&31 (unit),
// bg = wtid>>5 (4 groups x 4 batches). Row stride 260 floats; MMA uses LDS.128.
// Layer 0 writes output directly as bf16 hi/lo into g_Ah/g_Al.
#define PERS_SMEM ((128 * 260 + 16 * 260) * 4 + 4 * 128 * 17 * 8)
__global__ void __launch_bounds__(512) lstm_persist(const float* __restrict__ whh, int layer) {
    extern __shared__ float sm[];
    float* ws = sm;                        // [128][260] rows: g*32 + u
    float* hs = sm + 128 * 260;            // [16][260]
    ULL* part = (ULL*)(sm + 144 * 260);    // [4][128][17]

    int bx = blockIdx.x;
    int dir = bx & 1, bch = (bx >> 1) & 7, uch = bx >> 4;
    int grp = bx & 15;
    int tid = threadIdx.x;
    int wg = tid >> 7, wtid = tid & 127;
    int u = wtid & 31, bg = wtid >> 5;

    // epilogue cell: one (batch, unit) per thread
    int u_l = tid & 31, b_l = tid >> 5;            // u_l 0..31, b_l 0..15
    int uu_e = uch * 32 + u_l;
    int b_e = bch * 16 + b_l;
    int src = (b_l >> 2) * 32 + u_l;               // producing wtid
    int jj = b_l & 3;                              // j within producer

    // stage W_hh slice once: 128 rows (4 gates x 32 units) x 256 k = 16384 float2
    const float* wb = whh + (size_t)dir * 1024 * 256;
#pragma unroll 4
    for (int r = 0; r < 32; ++r) {
        int q = r * 512 + tid;
        int wrow = q >> 7, cc = q & 127;
        int gt = wrow >> 5, uw = wrow & 31;
        *(float2*)&ws[wrow * 260 + cc * 2] =
            *(const float2*)&wb[(size_t)(gt * 256 + uch * 32 + uw) * 256 + cc * 2];
    }

    float creg = 0.f;
    const int kbase = wg * 64;

    // prefetch xg for t = 0
    float xg[4];
    {
        int td0 = dir ? 255 : 0;
        size_t xb = ((size_t)b_e * 256 + td0) * 2048 + dir * 1024 + uu_e;
        xg[0] = xg_unpack(__ldcg(&g_xg[xb]));
        xg[1] = xg_unpack(__ldcg(&g_xg[xb + 256]));
        xg[2] = xg_unpack(__ldcg(&g_xg[xb + 512]));
        xg[3] = xg_unpack(__ldcg(&g_xg[xb + 768]));
    }

    for (int t = 0; t < 256; ++t) {
        int td = dir ? 255 - t : t;
        const float* hin = g_h + (t & 1) * (2 * 128 * 256);
        float* hout = g_h + ((t & 1) ^ 1) * (2 * 128 * 256);

        // stage h_{t-1}: 16 batches x 256 k = 2048 float2, 4 per thread (.cg)
        const float* hb = hin + (dir * 128 + bch * 16) * 256;
#pragma unroll
        for (int r = 0; r < 4; ++r) {
            int q = r * 512 + tid;
            int row = q >> 7, cc = q & 127;
            *(float2*)&hs[row * 260 + cc * 2] = __ldcg((const float2*)&hb[row * 256 + cc * 2]);
        }
        __syncthreads();

        // MMA: LDS.128 (4 k-floats per load)
        ULL acc[4][4] = {};
#pragma unroll
        for (int kq = 0; kq < 16; ++kq) {
            ulonglong2 hv[4], wv[4];
#pragma unroll
            for (int j = 0; j < 4; ++j)
                hv[j] = *(const ulonglong2*)&hs[(bg * 4 + j) * 260 + kbase + kq * 4];
#pragma unroll
            for (int g = 0; g < 4; ++g)
                wv[g] = *(const ulonglong2*)&ws[(g * 32 + u) * 260 + kbase + kq * 4];
#pragma unroll
            for (int g = 0; g < 4; ++g)
#pragma unroll
                for (int j = 0; j < 4; ++j) {
                    fma2(acc[g][j], hv[j].x, wv[g].x);
                    fma2(acc[g][j], hv[j].y, wv[g].y);
                }
        }

        // all wgs publish partials
        {
            ULL* pp = &part[(wg * 128 + wtid) * 17];
#pragma unroll
            for (int g = 0; g < 4; ++g)
#pragma unroll
                for (int j = 0; j < 4; ++j) pp[g * 4 + j] = acc[g][j];
        }
        __syncthreads();

        // distributed epilogue: one cell per thread
        float hn;
        {
            float gv[4];
#pragma unroll
            for (int g = 0; g < 4; ++g) {
                ULL s = part[src * 17 + g * 4 + jj];
#pragma unroll
                for (int w = 1; w < 4; ++w)
                    s = f2add(s, part[(w * 128 + src) * 17 + g * 4 + jj]);
                gv[g] = f2sum(s) + xg[g];
            }
            float cn = sigf(gv[1]) * creg + sigf(gv[0]) * tanhf(gv[2]);
            hn = sigf(gv[3]) * tanhf(cn);
            creg = cn;
            hout[(dir * 128 + b_e) * 256 + uu_e] = hn;
        }
        __syncthreads();

        // release-arrive; hide output store + next xg prefetch inside the wait
        if (tid == 0) bar_arrive_rel(&g_bar[grp]);
        {
            size_t oi = ((size_t)b_e * 256 + td) * 512 + dir * 256 + uu_e;
            if (layer == 0) {
                __nv_bfloat16 hh = __float2bfloat16_rn(hn);
                g_Ah[oi] = hh;
                g_Al[oi] = __float2bfloat16_rn(hn - __bfloat162float(hh));
            } else {
                g_out1[oi] = hn;
            }
        }
        if (t + 1 < 256) {
            int td2 = dir ? 255 - (t + 1) : t + 1;
            size_t xb = ((size_t)b_e * 256 + td2) * 2048 + dir * 1024 + uu_e;
            xg[0] = xg_unpack(__ldcg(&g_xg[xb]));
            xg[1] = xg_unpack(__ldcg(&g_xg[xb + 256]));
            xg[2] = xg_unpack(__ldcg(&g_xg[xb + 512]));
            xg[3] = xg_unpack(__ldcg(&g_xg[xb + 768]));
        }
        if (tid == 0) {
            unsigned tgt = 8u * (unsigned)(t + 1);
            while (bar_ld_acq(&g_bar[grp]) < tgt) { }
        }
        __syncthreads();
    }
}

// ---------------- LayerNorm + output projection (16 tokens/block) -------------
#define LN_SMEM (22 * 512 * 4 + 2 * 512 * 4 + 2 * 16 * 4 + 32 * 4)
__global__ void __launch_bounds__(256) lnfeats16(const float* __restrict__ lng,
                                                 const float* __restrict__ lnb,
                                                 const float* __restrict__ wo,
                                                 const float* __restrict__ bo) {
    extern __shared__ float lsm[];
    float* wos = lsm;                 // [22][512]
    float* row = lsm + 22 * 512;      // [2][512]
    float* red = row + 2 * 512;       // [2][16]
    float* bos = red + 2 * 16;        // [32]

    int tid = threadIdx.x;
    for (int q = tid; q < 22 * 512; q += 256) wos[q] = wo[q];
    if (tid < 22) bos[tid] = bo[tid];
    __syncthreads();

    int half = tid >> 7, t128 = tid & 127;
    int wid = t128 >> 5, lane = t128 & 31;

    for (int it = 0; it < 8; ++it) {
        int i = blockIdx.x * 16 + it * 2 + half;
        float4 v = *(const float4*)&g_out1[(size_t)i * 512 + t128 * 4];
        float s = v.x + v.y + v.z + v.w;
        float q = v.x * v.x + v.y * v.y + v.z * v.z + v.w * v.w;
#pragma unroll
        for (int o = 16; o; o >>= 1) {
            s += __shfl_xor_sync(0xffffffffu, s, o);
            q += __shfl_xor_sync(0xffffffffu, q, o);
        }
        if (!lane) { red[half * 16 + wid] = s; red[half * 16 + 4 + wid] = q; }
        __syncthreads();
        if (t128 == 0) {
            float S = red[half * 16 + 0] + red[half * 16 + 1] + red[half * 16 + 2] + red[half * 16 + 3];
            float Q = red[half * 16 + 4] + red[half * 16 + 5] + red[half * 16 + 6] + red[half * 16 + 7];
            float mu = S / 512.f;
            float var = Q / 512.f - mu * mu;
            red[half * 16 + 8] = mu;
            red[half * 16 + 9] = rsqrtf(var + 1e-5f);
        }
        __syncthreads();
        float mu = red[half * 16 + 8], rs = red[half * 16 + 9];
        int k = t128 * 4;
        float* rw = &row[half * 512];
        rw[k + 0] = (v.x - mu) * rs * lng[k + 0] + lnb[k + 0];
        rw[k + 1] = (v.y - mu) * rs * lng[k + 1] + lnb[k + 1];
        rw[k + 2] = (v.z - mu) * rs * lng[k + 2] + lnb[k + 2];
        rw[k + 3] = (v.w - mu) * rs * lng[k + 3] + lnb[k + 3];
        __syncthreads();
        for (int o = wid; o < 22; o += 4) {
            float a = 0.f;
            const float* wr = &wos[o * 512];
            for (int k2 = lane; k2 < 512; k2 += 32) a += rw[k2] * wr[k2];
#pragma unroll
            for (int off = 16; off; off >>= 1) a += __shfl_xor_sync(0xffffffffu, a, off);
            if (!lane) g_feats[(size_t)i * 22 + o] = a + bos[o];
        }
        __syncthreads();
    }
}

// ---------------- CRF forward + scores (one warp per batch) -------------------
__global__ void crf_k(const float* __restrict__ trans, const int* __restrict__ mask,
                      const int* __restrict__ tags) {
    __shared__ float tr[484];
    __shared__ float alpha[22];
    int b = blockIdx.x, j = threadIdx.x;
    for (int q = j; q < 484; q += 32) tr[q] = trans[q];
    const float* Fb = g_feats + (size_t)b * 256 * 22;
    __syncwarp();
    if (j < 22) alpha[j] = tr[20 * 22 + j] + Fb[j];
    __syncwarp();
    for (int t = 1; t < 256; ++t) {
        float aj = 0.f;
        if (j < 22) {
            float m = -1e30f;
#pragma unroll
            for (int i2 = 0; i2 < 22; ++i2) m = fmaxf(m, alpha[i2] + tr[i2 * 22 + j]);
            float sm = 0.f;
#pragma unroll
            for (int i2 = 0; i2 < 22; ++i2) sm += expf(alpha[i2] + tr[i2 * 22 + j] - m);
            aj = m + logf(sm) + Fb[t * 22 + j];
        }
        int mt = mask[b * 256 + t];
        __syncwarp();
        if (j < 22 && mt) alpha[j] = aj;
        __syncwarp();
    }
    float v = (j < 22) ? alpha[j] + tr[j * 22 + 21] : -1e30f;
    float m = v;
#pragma unroll
    for (int off = 16; off; off >>= 1) m = fmaxf(m, __shfl_xor_sync(0xffffffffu, m, off));
    float e = (j < 22) ? expf(v - m) : 0.f;
#pragma unroll
    for (int off = 16; off; off >>= 1) e += __shfl_xor_sync(0xffffffffu, e, off);
    float logZ = m + logf(e);

    const int* tg = tags + (size_t)b * 256;
    const int* mk = mask + b * 256;
    float emit = 0.f, trs = 0.f;
    int cnt = 0;
    for (int t = j; t < 256; t += 32) {
        if (mk[t]) {
            emit += Fb[t * 22 + tg[t]];
            cnt++;
            if (t >= 1) trs += tr[tg[t - 1] * 22 + tg[t]];
        }
    }
#pragma unroll
    for (int off = 16; off; off >>= 1) {
        emit += __shfl_xor_sync(0xffffffffu, emit, off);
        trs += __shfl_xor_sync(0xffffffffu, trs, off);
        cnt += __shfl_xor_sync(0xffffffffu, cnt, off);
    }
    if (!j) {
        trs += tr[20 * 22 + tg[0]];
        trs += tr[tg[cnt - 1] * 22 + 21];
        g_nll[b] = logZ - emit - trs;
    }
}

__global__ void reduce_nll(float* out) {
    int tid = threadIdx.x;
    float v = g_nll[tid];
#pragma unroll
    for (int off = 16; off; off >>= 1) v += __shfl_xor_sync(0xffffffffu, v, off);
    __shared__ float r[4];
    if (!(tid & 31)) r[tid >> 5] = v;
    __syncthreads();
    if (!tid) out[0] = (r[0] + r[1] + r[2] + r[3]) / 128.f;
}

// ---------------- launcher ----------------
extern "C" void kernel_launch(void* const* d_in, const int* in_sizes, int n_in,
                              void* d_out, int out_size) {
    const float* emb    = (const float*)d_in[0];
    const float* w_ih0  = (const float*)d_in[1];
    const float* w_hh0  = (const float*)d_in[2];
    const float* b_ih0  = (const float*)d_in[3];
    const float* b_hh0  = (const float*)d_in[4];
    const float* w_ih1  = (const float*)d_in[5];
    const float* w_hh1  = (const float*)d_in[6];
    const float* b_ih1  = (const float*)d_in[7];
    const float* b_hh1  = (const float*)d_in[8];
    const float* ln_g   = (const float*)d_in[9];
    const float* ln_b   = (const float*)d_in[10];
    const float* w_out  = (const float*)d_in[11];
    const float* b_out  = (const float*)d_in[12];
    const float* trans  = (const float*)d_in[13];
    const int* words    = (const int*)d_in[14];
    const int* mask     = (const int*)d_in[15];
    const int* tags     = (const int*)d_in[16];
    float* out = (float*)d_out;

    cudaFuncSetAttribute(lstm_persist, cudaFuncAttributeMaxDynamicSharedMemorySize, PERS_SMEM);
    cudaFuncSetAttribute(gemm_tc<256>, cudaFuncAttributeMaxDynamicSharedMemorySize, GT_SMEM);
    cudaFuncSetAttribute(gemm_tc<512>, cudaFuncAttributeMaxDynamicSharedMemorySize, GT_SMEM);
    cudaFuncSetAttribute(lnfeats16, cudaFuncAttributeMaxDynamicSharedMemorySize, LN_SMEM);

    // layer 0
    embed_bf<<<32768, 256>>>(emb, words);
    conv_w<<<2048, 256>>>(w_ih0);
    gemm_tc<256><<<dim3(8, 256), 256, GT_SMEM>>>(b_ih0, b_hh0);
    init_hc<<<128, 256>>>();
    lstm_persist<<<128, 512, PERS_SMEM>>>(w_hh0, 0);   // writes bf16 hi/lo out
    // layer 1
    conv_w<<<4096, 256>>>(w_ih1);
    gemm_tc<512><<<dim3(8, 256), 256, GT_SMEM>>>(b_ih1, b_hh1);
    init_hc<<<128, 256>>>();
    lstm_persist<<<128, 512, PERS_SMEM>>>(w_hh1, 1);
    // head
    lnfeats16<<<2048, 256, LN_SMEM>>>(ln_g, ln_b, w_out, b_out);
    crf_k<<<128, 32>>>(trans, mask, tags);
    reduce_nll<<<1, 128>>>(out);
}